// round 5
// baseline (speedup 1.0000x reference)
#include <cuda_runtime.h>
#include <math.h>

#define B_   8
#define HW_  4096
#define C_   256
#define NT_  (B_ * HW_)   // 32768 tokens

// ---- scratch (device globals: allocation-free) ----
static __device__ float g_h [(size_t)NT_ * C_];
static __device__ float g_q [(size_t)NT_ * C_];
static __device__ float g_k [(size_t)NT_ * C_];
static __device__ float g_v [(size_t)NT_ * C_];
static __device__ float g_ao[(size_t)NT_ * C_];

// =====================================================================
// LayerNorm: one warp per token (C=256 -> 8 floats/lane)
// =====================================================================
__global__ __launch_bounds__(256) void ln_kernel(
    const float* __restrict__ x, const float* __restrict__ gamma,
    const float* __restrict__ beta, float* __restrict__ out)
{
    int token = blockIdx.x * 8 + (threadIdx.x >> 5);
    int lane  = threadIdx.x & 31;
    const float4* xr = (const float4*)(x + (size_t)token * C_);
    float4 a = xr[lane];
    float4 b = xr[lane + 32];
    float s  = a.x + a.y + a.z + a.w + b.x + b.y + b.z + b.w;
    float s2 = a.x*a.x + a.y*a.y + a.z*a.z + a.w*a.w
             + b.x*b.x + b.y*b.y + b.z*b.z + b.w*b.w;
#pragma unroll
    for (int o = 16; o; o >>= 1) {
        s  += __shfl_xor_sync(0xffffffffu, s,  o);
        s2 += __shfl_xor_sync(0xffffffffu, s2, o);
    }
    float mu   = s * (1.0f / C_);
    float rstd = rsqrtf(s2 * (1.0f / C_) - mu * mu + 1e-5f);
    float4 g0  = ((const float4*)gamma)[lane];
    float4 g1  = ((const float4*)gamma)[lane + 32];
    float4 be0 = ((const float4*)beta)[lane];
    float4 be1 = ((const float4*)beta)[lane + 32];
    float4 o0, o1;
    o0.x = (a.x - mu) * rstd * g0.x + be0.x;
    o0.y = (a.y - mu) * rstd * g0.y + be0.y;
    o0.z = (a.z - mu) * rstd * g0.z + be0.z;
    o0.w = (a.w - mu) * rstd * g0.w + be0.w;
    o1.x = (b.x - mu) * rstd * g1.x + be1.x;
    o1.y = (b.y - mu) * rstd * g1.y + be1.y;
    o1.z = (b.z - mu) * rstd * g1.z + be1.z;
    o1.w = (b.w - mu) * rstd * g1.w + be1.w;
    float4* orow = (float4*)(out + (size_t)token * C_);
    orow[lane]      = o0;
    orow[lane + 32] = o1;
}

// =====================================================================
// SGEMM: out[M,256] = A[M,256] @ W[256,256] + bias (+ resid)
// BM=128, BN=128, BK=16, 256 threads, 8x8 per thread
// grid: (N/128=2, M/128)
// =====================================================================
__global__ __launch_bounds__(256) void gemm_kernel(
    const float* __restrict__ A, const float* __restrict__ W,
    const float* __restrict__ bias, const float* __restrict__ resid,
    float* __restrict__ out)
{
    __shared__ float As[16][128];   // transposed: As[k][m]
    __shared__ float Bs[16][128];   // Bs[k][n]
    int tid = threadIdx.x;
    int m0  = blockIdx.y * 128;
    int n0  = blockIdx.x * 128;
    int ty  = tid >> 4, tx = tid & 15;

    float acc[8][8];
#pragma unroll
    for (int i = 0; i < 8; ++i)
#pragma unroll
        for (int j = 0; j < 8; ++j) acc[i][j] = 0.0f;

    for (int k0 = 0; k0 < 256; k0 += 16) {
#pragma unroll
        for (int r = 0; r < 2; ++r) {
            int idx = tid + r * 256;
            int m = idx >> 2, kq = idx & 3;
            float4 v = *(const float4*)(A + (size_t)(m0 + m) * C_ + k0 + kq * 4);
            As[kq*4 + 0][m] = v.x;
            As[kq*4 + 1][m] = v.y;
            As[kq*4 + 2][m] = v.z;
            As[kq*4 + 3][m] = v.w;
        }
#pragma unroll
        for (int r = 0; r < 2; ++r) {
            int idx = tid + r * 256;
            int k = idx >> 5, nq = idx & 31;
            *(float4*)&Bs[k][nq*4] =
                *(const float4*)(W + (size_t)(k0 + k) * C_ + n0 + nq * 4);
        }
        __syncthreads();
#pragma unroll
        for (int k = 0; k < 16; ++k) {
            float a[8], b[8];
            *(float4*)&a[0] = *(const float4*)&As[k][ty*8];
            *(float4*)&a[4] = *(const float4*)&As[k][ty*8 + 4];
            *(float4*)&b[0] = *(const float4*)&Bs[k][tx*8];
            *(float4*)&b[4] = *(const float4*)&Bs[k][tx*8 + 4];
#pragma unroll
            for (int i = 0; i < 8; ++i)
#pragma unroll
                for (int j = 0; j < 8; ++j)
                    acc[i][j] += a[i] * b[j];
        }
        __syncthreads();
    }

    float bs[8];
    *(float4*)&bs[0] = *(const float4*)(bias + n0 + tx*8);
    *(float4*)&bs[4] = *(const float4*)(bias + n0 + tx*8 + 4);
#pragma unroll
    for (int i = 0; i < 8; ++i) {
        size_t off = (size_t)(m0 + ty*8 + i) * C_ + n0 + tx*8;
        float r0[4], r1[4];
#pragma unroll
        for (int j = 0; j < 4; ++j) r0[j] = acc[i][j]     + bs[j];
#pragma unroll
        for (int j = 0; j < 4; ++j) r1[j] = acc[i][j + 4] + bs[j + 4];
        if (resid) {
            float4 x0 = *(const float4*)(resid + off);
            float4 x1 = *(const float4*)(resid + off + 4);
            r0[0] += x0.x; r0[1] += x0.y; r0[2] += x0.z; r0[3] += x0.w;
            r1[0] += x1.x; r1[1] += x1.y; r1[2] += x1.z; r1[3] += x1.w;
        }
        *(float4*)(out + off)     = *(float4*)r0;
        *(float4*)(out + off + 4) = *(float4*)r1;
    }
}

// =====================================================================
// Flash attention, fp32. BM=64 queries/CTA, BN=64 keys/iter, C=256.
// 256 threads as 16x16; 4x4 S-tile, 4x16 O-tile per thread.
// grid: (HW/64, B)
// =====================================================================
#define AT_BM 64
#define AT_BN 64
// smem (floats): Qs[256][64] | Ks[64][64] | Ps[64][65] | Vs[64][64]
#define ATTN_SMEM ((256*64 + 64*64 + 64*65 + 64*64) * 4)

__global__ __launch_bounds__(256) void attn_kernel(
    const float* __restrict__ Q, const float* __restrict__ K,
    const float* __restrict__ V, float* __restrict__ O)
{
    extern __shared__ float sm[];
    float (*Qs)[AT_BM]     = (float(*)[AT_BM])(sm);
    float (*Ks)[AT_BN]     = (float(*)[AT_BN])(sm + 256*64);
    float (*Ps)[AT_BN + 1] = (float(*)[AT_BN + 1])(sm + 256*64 + 64*64);
    float (*Vs)[64]        = (float(*)[64])(sm + 256*64 + 64*64 + 64*65);

    int tid = threadIdx.x;
    int tx  = tid & 15, ty = tid >> 4;
    int b   = blockIdx.y;
    int m0  = blockIdx.x * AT_BM;
    const float* Qb = Q + ((size_t)b * HW_ + m0) * C_;
    const float* Kb = K + (size_t)b * HW_ * C_;
    const float* Vb = V + (size_t)b * HW_ * C_;

    // Q tile -> smem, transposed, pre-scaled by C^-0.5 = 1/16
    const float scale = 0.0625f;
    for (int i = tid; i < AT_BM * C_ / 4; i += 256) {
        int m = i >> 6, c4 = i & 63;
        float4 v = *(const float4*)(Qb + (size_t)m * C_ + c4 * 4);
        int c = c4 * 4;
        Qs[c + 0][m] = v.x * scale;
        Qs[c + 1][m] = v.y * scale;
        Qs[c + 2][m] = v.z * scale;
        Qs[c + 3][m] = v.w * scale;
    }

    float acc[4][16];
#pragma unroll
    for (int i = 0; i < 4; ++i)
#pragma unroll
        for (int c = 0; c < 16; ++c) acc[i][c] = 0.0f;
    float mrow[4], lrow[4];
#pragma unroll
    for (int i = 0; i < 4; ++i) { mrow[i] = -INFINITY; lrow[i] = 0.0f; }

    for (int t = 0; t < HW_ / AT_BN; ++t) {
        const float* Kt = Kb + (size_t)t * AT_BN * C_;

        // ---- S = Q @ K^T (accumulate over 4 chunks of 64 k-dims) ----
        float S[4][4];
#pragma unroll
        for (int i = 0; i < 4; ++i)
#pragma unroll
            for (int j = 0; j < 4; ++j) S[i][j] = 0.0f;

#pragma unroll 1
        for (int kc = 0; kc < C_; kc += 64) {
            __syncthreads();
#pragma unroll
            for (int r = 0; r < 4; ++r) {
                int idx = tid + r * 256;
                int n = idx >> 4, c4 = idx & 15;
                float4 v = *(const float4*)(Kt + (size_t)n * C_ + kc + c4 * 4);
                int c = c4 * 4;
                Ks[c + 0][n] = v.x; Ks[c + 1][n] = v.y;
                Ks[c + 2][n] = v.z; Ks[c + 3][n] = v.w;
            }
            __syncthreads();
#pragma unroll 8
            for (int k = 0; k < 64; ++k) {
                float4 qa  = *(const float4*)&Qs[kc + k][ty * 4];
                float4 kb4 = *(const float4*)&Ks[k][tx * 4];
                float qf[4] = {qa.x, qa.y, qa.z, qa.w};
                float kf[4] = {kb4.x, kb4.y, kb4.z, kb4.w};
#pragma unroll
                for (int i = 0; i < 4; ++i)
#pragma unroll
                    for (int j = 0; j < 4; ++j)
                        S[i][j] += qf[i] * kf[j];
            }
        }

        // ---- online softmax (rows shared by the 16 threads of a tx-group) ----
#pragma unroll
        for (int i = 0; i < 4; ++i) {
            float mt = fmaxf(fmaxf(S[i][0], S[i][1]), fmaxf(S[i][2], S[i][3]));
#pragma unroll
            for (int o = 8; o; o >>= 1)
                mt = fmaxf(mt, __shfl_xor_sync(0xffffffffu, mt, o));
            float mn = fmaxf(mrow[i], mt);
            float al = __expf(mrow[i] - mn);
            mrow[i] = mn;
            float rs = 0.0f;
#pragma unroll
            for (int j = 0; j < 4; ++j) { S[i][j] = __expf(S[i][j] - mn); rs += S[i][j]; }
#pragma unroll
            for (int o = 8; o; o >>= 1)
                rs += __shfl_xor_sync(0xffffffffu, rs, o);
            lrow[i] = lrow[i] * al + rs;
#pragma unroll
            for (int c = 0; c < 16; ++c) acc[i][c] *= al;
        }

        // ---- P to smem ----
#pragma unroll
        for (int i = 0; i < 4; ++i)
#pragma unroll
            for (int j = 0; j < 4; ++j)
                Ps[ty*4 + i][tx*4 + j] = S[i][j];

        // ---- O += P @ V  (4 chunks of 64 output cols) ----
#pragma unroll
        for (int cc = 0; cc < 4; ++cc) {
            __syncthreads();   // Ps visible (cc=0); Vs reuse safe (cc>0)
#pragma unroll
            for (int r = 0; r < 4; ++r) {
                int idx = tid + r * 256;
                int n = idx >> 4, c4 = idx & 15;
                *(float4*)&Vs[n][c4*4] =
                    *(const float4*)(Vb + (size_t)(t*AT_BN + n) * C_ + cc*64 + c4*4);
            }
            __syncthreads();
#pragma unroll 8
            for (int n = 0; n < 64; ++n) {
                float4 v4 = *(const float4*)&Vs[n][tx * 4];
                float vf[4] = {v4.x, v4.y, v4.z, v4.w};
                float pp[4];
#pragma unroll
                for (int i = 0; i < 4; ++i) pp[i] = Ps[ty*4 + i][n];
#pragma unroll
                for (int i = 0; i < 4; ++i)
#pragma unroll
                    for (int j = 0; j < 4; ++j)
                        acc[i][cc*4 + j] += pp[i] * vf[j];
            }
        }
    }

    // ---- epilogue: O /= l ----
    float* Ob = O + ((size_t)b * HW_ + m0) * C_;
#pragma unroll
    for (int i = 0; i < 4; ++i) {
        float inv = 1.0f / lrow[i];
#pragma unroll
        for (int cc = 0; cc < 4; ++cc) {
            float o4[4];
#pragma unroll
            for (int j = 0; j < 4; ++j) o4[j] = acc[i][cc*4 + j] * inv;
            *(float4*)(Ob + (size_t)(ty*4 + i) * C_ + cc*64 + tx*4) = *(float4*)o4;
        }
    }
}

// =====================================================================
extern "C" void kernel_launch(void* const* d_in, const int* in_sizes, int n_in,
                              void* d_out, int out_size)
{
    const float* x   = (const float*)d_in[0];
    const float* gam = (const float*)d_in[1];
    const float* bet = (const float*)d_in[2];
    const float* wq  = (const float*)d_in[3];
    const float* bq  = (const float*)d_in[4];
    const float* wk  = (const float*)d_in[5];
    const float* bk  = (const float*)d_in[6];
    const float* wv  = (const float*)d_in[7];
    const float* bv  = (const float*)d_in[8];
    const float* wo  = (const float*)d_in[9];
    const float* bo  = (const float*)d_in[10];
    float* out = (float*)d_out;

    float *h, *q, *k, *v, *ao;
    cudaGetSymbolAddress((void**)&h,  g_h);
    cudaGetSymbolAddress((void**)&q,  g_q);
    cudaGetSymbolAddress((void**)&k,  g_k);
    cudaGetSymbolAddress((void**)&v,  g_v);
    cudaGetSymbolAddress((void**)&ao, g_ao);

    cudaFuncSetAttribute(attn_kernel,
                         cudaFuncAttributeMaxDynamicSharedMemorySize, ATTN_SMEM);

    ln_kernel<<<NT_ / 8, 256>>>(x, gam, bet, h);

    dim3 gg(C_ / 128, NT_ / 128);   // (2, 256)
    gemm_kernel<<<gg, 256>>>(h, wq, bq, nullptr, q);
    gemm_kernel<<<gg, 256>>>(h, wk, bk, nullptr, k);
    gemm_kernel<<<gg, 256>>>(h, wv, bv, nullptr, v);

    attn_kernel<<<dim3(HW_ / AT_BM, B_), 256, ATTN_SMEM>>>(q, k, v, ao);

    gemm_kernel<<<gg, 256>>>(ao, wo, bo, x, out);
}

// round 6
// speedup vs baseline: 1.0015x; 1.0015x over previous
#include <cuda_runtime.h>
#include <math.h>

#define B_   8
#define HW_  4096
#define C_   256
#define NT_  (B_ * HW_)   // 32768 tokens

// ---- scratch (device globals: allocation-free) ----
static __device__ float g_h [(size_t)NT_ * C_];
static __device__ float g_q [(size_t)NT_ * C_];
static __device__ float g_k [(size_t)NT_ * C_];
static __device__ float g_v [(size_t)NT_ * C_];
static __device__ float g_ao[(size_t)NT_ * C_];

// =====================================================================
// LayerNorm: one warp per token (C=256 -> 8 floats/lane)
// =====================================================================
__global__ __launch_bounds__(256) void ln_kernel(
    const float* __restrict__ x, const float* __restrict__ gamma,
    const float* __restrict__ beta, float* __restrict__ out)
{
    int token = blockIdx.x * 8 + (threadIdx.x >> 5);
    int lane  = threadIdx.x & 31;
    const float4* xr = (const float4*)(x + (size_t)token * C_);
    float4 a = xr[lane];
    float4 b = xr[lane + 32];
    float s  = a.x + a.y + a.z + a.w + b.x + b.y + b.z + b.w;
    float s2 = a.x*a.x + a.y*a.y + a.z*a.z + a.w*a.w
             + b.x*b.x + b.y*b.y + b.z*b.z + b.w*b.w;
#pragma unroll
    for (int o = 16; o; o >>= 1) {
        s  += __shfl_xor_sync(0xffffffffu, s,  o);
        s2 += __shfl_xor_sync(0xffffffffu, s2, o);
    }
    float mu   = s * (1.0f / C_);
    float rstd = rsqrtf(s2 * (1.0f / C_) - mu * mu + 1e-5f);
    float4 g0  = ((const float4*)gamma)[lane];
    float4 g1  = ((const float4*)gamma)[lane + 32];
    float4 be0 = ((const float4*)beta)[lane];
    float4 be1 = ((const float4*)beta)[lane + 32];
    float4 o0, o1;
    o0.x = (a.x - mu) * rstd * g0.x + be0.x;
    o0.y = (a.y - mu) * rstd * g0.y + be0.y;
    o0.z = (a.z - mu) * rstd * g0.z + be0.z;
    o0.w = (a.w - mu) * rstd * g0.w + be0.w;
    o1.x = (b.x - mu) * rstd * g1.x + be1.x;
    o1.y = (b.y - mu) * rstd * g1.y + be1.y;
    o1.z = (b.z - mu) * rstd * g1.z + be1.z;
    o1.w = (b.w - mu) * rstd * g1.w + be1.w;
    float4* orow = (float4*)(out + (size_t)token * C_);
    orow[lane]      = o0;
    orow[lane + 32] = o1;
}

// =====================================================================
// SGEMM: out[M,256] = A[M,256] @ W[256,256] + bias (+ resid)
// BM=128, BN=128, BK=16, 256 threads, 8x8 per thread
// grid: (N/128=2, M/128)
// =====================================================================
__global__ __launch_bounds__(256) void gemm_kernel(
    const float* __restrict__ A, const float* __restrict__ W,
    const float* __restrict__ bias, const float* __restrict__ resid,
    float* __restrict__ out)
{
    __shared__ float As[16][128];   // transposed: As[k][m]
    __shared__ float Bs[16][128];   // Bs[k][n]
    int tid = threadIdx.x;
    int m0  = blockIdx.y * 128;
    int n0  = blockIdx.x * 128;
    int ty  = tid >> 4, tx = tid & 15;

    float acc[8][8];
#pragma unroll
    for (int i = 0; i < 8; ++i)
#pragma unroll
        for (int j = 0; j < 8; ++j) acc[i][j] = 0.0f;

    for (int k0 = 0; k0 < 256; k0 += 16) {
#pragma unroll
        for (int r = 0; r < 2; ++r) {
            int idx = tid + r * 256;
            int m = idx >> 2, kq = idx & 3;
            float4 v = *(const float4*)(A + (size_t)(m0 + m) * C_ + k0 + kq * 4);
            As[kq*4 + 0][m] = v.x;
            As[kq*4 + 1][m] = v.y;
            As[kq*4 + 2][m] = v.z;
            As[kq*4 + 3][m] = v.w;
        }
#pragma unroll
        for (int r = 0; r < 2; ++r) {
            int idx = tid + r * 256;
            int k = idx >> 5, nq = idx & 31;
            *(float4*)&Bs[k][nq*4] =
                *(const float4*)(W + (size_t)(k0 + k) * C_ + n0 + nq * 4);
        }
        __syncthreads();
#pragma unroll
        for (int k = 0; k < 16; ++k) {
            float a[8], b[8];
            *(float4*)&a[0] = *(const float4*)&As[k][ty*8];
            *(float4*)&a[4] = *(const float4*)&As[k][ty*8 + 4];
            *(float4*)&b[0] = *(const float4*)&Bs[k][tx*8];
            *(float4*)&b[4] = *(const float4*)&Bs[k][tx*8 + 4];
#pragma unroll
            for (int i = 0; i < 8; ++i)
#pragma unroll
                for (int j = 0; j < 8; ++j)
                    acc[i][j] += a[i] * b[j];
        }
        __syncthreads();
    }

    float bs[8];
    *(float4*)&bs[0] = *(const float4*)(bias + n0 + tx*8);
    *(float4*)&bs[4] = *(const float4*)(bias + n0 + tx*8 + 4);
#pragma unroll
    for (int i = 0; i < 8; ++i) {
        size_t off = (size_t)(m0 + ty*8 + i) * C_ + n0 + tx*8;
        float r0[4], r1[4];
#pragma unroll
        for (int j = 0; j < 4; ++j) r0[j] = acc[i][j]     + bs[j];
#pragma unroll
        for (int j = 0; j < 4; ++j) r1[j] = acc[i][j + 4] + bs[j + 4];
        if (resid) {
            float4 x0 = *(const float4*)(resid + off);
            float4 x1 = *(const float4*)(resid + off + 4);
            r0[0] += x0.x; r0[1] += x0.y; r0[2] += x0.z; r0[3] += x0.w;
            r1[0] += x1.x; r1[1] += x1.y; r1[2] += x1.z; r1[3] += x1.w;
        }
        *(float4*)(out + off)     = *(float4*)r0;
        *(float4*)(out + off + 4) = *(float4*)r1;
    }
}

// =====================================================================
// Flash attention, fp32. BM=64 queries/CTA, BN=64 keys/iter, C=256.
// 256 threads as 16x16; 4x4 S-tile, 4x16 O-tile per thread.
// grid: (HW/64, B)
// =====================================================================
#define AT_BM 64
#define AT_BN 64
// smem (floats): Qs[256][64] | Ks[64][64] | Ps[64][65] | Vs[64][64]
#define ATTN_SMEM ((256*64 + 64*64 + 64*65 + 64*64) * 4)

__global__ __launch_bounds__(256) void attn_kernel(
    const float* __restrict__ Q, const float* __restrict__ K,
    const float* __restrict__ V, float* __restrict__ O)
{
    extern __shared__ float sm[];
    float (*Qs)[AT_BM]     = (float(*)[AT_BM])(sm);
    float (*Ks)[AT_BN]     = (float(*)[AT_BN])(sm + 256*64);
    float (*Ps)[AT_BN + 1] = (float(*)[AT_BN + 1])(sm + 256*64 + 64*64);
    float (*Vs)[64]        = (float(*)[64])(sm + 256*64 + 64*64 + 64*65);

    int tid = threadIdx.x;
    int tx  = tid & 15, ty = tid >> 4;
    int b   = blockIdx.y;
    int m0  = blockIdx.x * AT_BM;
    const float* Qb = Q + ((size_t)b * HW_ + m0) * C_;
    const float* Kb = K + (size_t)b * HW_ * C_;
    const float* Vb = V + (size_t)b * HW_ * C_;

    // Q tile -> smem, transposed, pre-scaled by C^-0.5 = 1/16
    const float scale = 0.0625f;
    for (int i = tid; i < AT_BM * C_ / 4; i += 256) {
        int m = i >> 6, c4 = i & 63;
        float4 v = *(const float4*)(Qb + (size_t)m * C_ + c4 * 4);
        int c = c4 * 4;
        Qs[c + 0][m] = v.x * scale;
        Qs[c + 1][m] = v.y * scale;
        Qs[c + 2][m] = v.z * scale;
        Qs[c + 3][m] = v.w * scale;
    }

    float acc[4][16];
#pragma unroll
    for (int i = 0; i < 4; ++i)
#pragma unroll
        for (int c = 0; c < 16; ++c) acc[i][c] = 0.0f;
    float mrow[4], lrow[4];
#pragma unroll
    for (int i = 0; i < 4; ++i) { mrow[i] = -INFINITY; lrow[i] = 0.0f; }

    for (int t = 0; t < HW_ / AT_BN; ++t) {
        const float* Kt = Kb + (size_t)t * AT_BN * C_;

        // ---- S = Q @ K^T (accumulate over 4 chunks of 64 k-dims) ----
        float S[4][4];
#pragma unroll
        for (int i = 0; i < 4; ++i)
#pragma unroll
            for (int j = 0; j < 4; ++j) S[i][j] = 0.0f;

#pragma unroll 1
        for (int kc = 0; kc < C_; kc += 64) {
            __syncthreads();
#pragma unroll
            for (int r = 0; r < 4; ++r) {
                int idx = tid + r * 256;
                int n = idx >> 4, c4 = idx & 15;
                float4 v = *(const float4*)(Kt + (size_t)n * C_ + kc + c4 * 4);
                int c = c4 * 4;
                Ks[c + 0][n] = v.x; Ks[c + 1][n] = v.y;
                Ks[c + 2][n] = v.z; Ks[c + 3][n] = v.w;
            }
            __syncthreads();
#pragma unroll 8
            for (int k = 0; k < 64; ++k) {
                float4 qa  = *(const float4*)&Qs[kc + k][ty * 4];
                float4 kb4 = *(const float4*)&Ks[k][tx * 4];
                float qf[4] = {qa.x, qa.y, qa.z, qa.w};
                float kf[4] = {kb4.x, kb4.y, kb4.z, kb4.w};
#pragma unroll
                for (int i = 0; i < 4; ++i)
#pragma unroll
                    for (int j = 0; j < 4; ++j)
                        S[i][j] += qf[i] * kf[j];
            }
        }

        // ---- online softmax (rows shared by the 16 threads of a tx-group) ----
#pragma unroll
        for (int i = 0; i < 4; ++i) {
            float mt = fmaxf(fmaxf(S[i][0], S[i][1]), fmaxf(S[i][2], S[i][3]));
#pragma unroll
            for (int o = 8; o; o >>= 1)
                mt = fmaxf(mt, __shfl_xor_sync(0xffffffffu, mt, o));
            float mn = fmaxf(mrow[i], mt);
            float al = __expf(mrow[i] - mn);
            mrow[i] = mn;
            float rs = 0.0f;
#pragma unroll
            for (int j = 0; j < 4; ++j) { S[i][j] = __expf(S[i][j] - mn); rs += S[i][j]; }
#pragma unroll
            for (int o = 8; o; o >>= 1)
                rs += __shfl_xor_sync(0xffffffffu, rs, o);
            lrow[i] = lrow[i] * al + rs;
#pragma unroll
            for (int c = 0; c < 16; ++c) acc[i][c] *= al;
        }

        // ---- P to smem ----
#pragma unroll
        for (int i = 0; i < 4; ++i)
#pragma unroll
            for (int j = 0; j < 4; ++j)
                Ps[ty*4 + i][tx*4 + j] = S[i][j];

        // ---- O += P @ V  (4 chunks of 64 output cols) ----
#pragma unroll
        for (int cc = 0; cc < 4; ++cc) {
            __syncthreads();   // Ps visible (cc=0); Vs reuse safe (cc>0)
#pragma unroll
            for (int r = 0; r < 4; ++r) {
                int idx = tid + r * 256;
                int n = idx >> 4, c4 = idx & 15;
                *(float4*)&Vs[n][c4*4] =
                    *(const float4*)(Vb + (size_t)(t*AT_BN + n) * C_ + cc*64 + c4*4);
            }
            __syncthreads();
#pragma unroll 8
            for (int n = 0; n < 64; ++n) {
                float4 v4 = *(const float4*)&Vs[n][tx * 4];
                float vf[4] = {v4.x, v4.y, v4.z, v4.w};
                float pp[4];
#pragma unroll
                for (int i = 0; i < 4; ++i) pp[i] = Ps[ty*4 + i][n];
#pragma unroll
                for (int i = 0; i < 4; ++i)
#pragma unroll
                    for (int j = 0; j < 4; ++j)
                        acc[i][cc*4 + j] += pp[i] * vf[j];
            }
        }
    }

    // ---- epilogue: O /= l ----
    float* Ob = O + ((size_t)b * HW_ + m0) * C_;
#pragma unroll
    for (int i = 0; i < 4; ++i) {
        float inv = 1.0f / lrow[i];
#pragma unroll
        for (int cc = 0; cc < 4; ++cc) {
            float o4[4];
#pragma unroll
            for (int j = 0; j < 4; ++j) o4[j] = acc[i][cc*4 + j] * inv;
            *(float4*)(Ob + (size_t)(ty*4 + i) * C_ + cc*64 + tx*4) = *(float4*)o4;
        }
    }
}

// =====================================================================
extern "C" void kernel_launch(void* const* d_in, const int* in_sizes, int n_in,
                              void* d_out, int out_size)
{
    const float* x   = (const float*)d_in[0];
    const float* gam = (const float*)d_in[1];
    const float* bet = (const float*)d_in[2];
    const float* wq  = (const float*)d_in[3];
    const float* bq  = (const float*)d_in[4];
    const float* wk  = (const float*)d_in[5];
    const float* bk  = (const float*)d_in[6];
    const float* wv  = (const float*)d_in[7];
    const float* bv  = (const float*)d_in[8];
    const float* wo  = (const float*)d_in[9];
    const float* bo  = (const float*)d_in[10];
    float* out = (float*)d_out;

    float *h, *q, *k, *v, *ao;
    cudaGetSymbolAddress((void**)&h,  g_h);
    cudaGetSymbolAddress((void**)&q,  g_q);
    cudaGetSymbolAddress((void**)&k,  g_k);
    cudaGetSymbolAddress((void**)&v,  g_v);
    cudaGetSymbolAddress((void**)&ao, g_ao);

    cudaFuncSetAttribute(attn_kernel,
                         cudaFuncAttributeMaxDynamicSharedMemorySize, ATTN_SMEM);

    ln_kernel<<<NT_ / 8, 256>>>(x, gam, bet, h);

    dim3 gg(C_ / 128, NT_ / 128);   // (2, 256)
    gemm_kernel<<<gg, 256>>>(h, wq, bq, nullptr, q);
    gemm_kernel<<<gg, 256>>>(h, wk, bk, nullptr, k);
    gemm_kernel<<<gg, 256>>>(h, wv, bv, nullptr, v);

    attn_kernel<<<dim3(HW_ / AT_BM, B_), 256, ATTN_SMEM>>>(q, k, v, ao);

    gemm_kernel<<<gg, 256>>>(ao, wo, bo, x, out);
}

// round 8
// speedup vs baseline: 3.2900x; 3.2850x over previous
#include <cuda_runtime.h>
#include <cuda_bf16.h>
#include <math.h>
#include <stdint.h>

#define B_   8
#define HW_  4096
#define C_   256
#define NT_  (B_ * HW_)

static __device__ float g_h [(size_t)NT_ * C_];
static __device__ float g_q [(size_t)NT_ * C_];
static __device__ float g_k [(size_t)NT_ * C_];
static __device__ float g_v [(size_t)NT_ * C_];
static __device__ float g_ao[(size_t)NT_ * C_];
static __device__ unsigned short g_kh[(size_t)NT_ * C_];
static __device__ unsigned short g_kl[(size_t)NT_ * C_];
static __device__ unsigned short g_vh[(size_t)NT_ * C_];
static __device__ unsigned short g_vl[(size_t)NT_ * C_];

// ---------------- helpers (sm_80-level PTX only: no tcgen05) ----------------
__device__ __forceinline__ uint32_t smem_u32(const void* p) {
    uint32_t a;
    asm("{ .reg .u64 t; cvta.to.shared.u64 t, %1; cvt.u32.u64 %0, t; }" : "=r"(a) : "l"(p));
    return a;
}
__device__ __forceinline__ void cpa16(uint32_t s, const void* g) {
    asm volatile("cp.async.cg.shared.global [%0], [%1], 16;" :: "r"(s), "l"(g));
}
#define CP_COMMIT() asm volatile("cp.async.commit_group;" ::: "memory")
#define CP_WAIT()   asm volatile("cp.async.wait_group 0;" ::: "memory")
#define LDSM4(R, A) \
    asm volatile("ldmatrix.sync.aligned.m8n8.x4.shared.b16 {%0,%1,%2,%3}, [%4];" \
        : "=r"((R)[0]), "=r"((R)[1]), "=r"((R)[2]), "=r"((R)[3]) : "r"(A))
#define LDSM4T(R, A) \
    asm volatile("ldmatrix.sync.aligned.m8n8.x4.trans.shared.b16 {%0,%1,%2,%3}, [%4];" \
        : "=r"((R)[0]), "=r"((R)[1]), "=r"((R)[2]), "=r"((R)[3]) : "r"(A))
__device__ __forceinline__ void mma16816(float* c, const uint32_t* a, uint32_t b0, uint32_t b1) {
    asm volatile("mma.sync.aligned.m16n8k16.row.col.f32.bf16.bf16.f32 "
                 "{%0,%1,%2,%3}, {%4,%5,%6,%7}, {%8,%9}, {%0,%1,%2,%3};"
                 : "+f"(c[0]), "+f"(c[1]), "+f"(c[2]), "+f"(c[3])
                 : "r"(a[0]), "r"(a[1]), "r"(a[2]), "r"(a[3]), "r"(b0), "r"(b1));
}
__device__ __forceinline__ uint32_t pack2(__nv_bfloat16 a, __nv_bfloat16 b) {
    __nv_bfloat162 t; t.x = a; t.y = b;
    return *reinterpret_cast<uint32_t*>(&t);
}
__device__ __forceinline__ void split2(float f, __nv_bfloat16& h, __nv_bfloat16& l) {
    h = __float2bfloat16(f);
    l = __float2bfloat16(f - __bfloat162float(h));
}

// ---------------- LayerNorm ----------------
__global__ __launch_bounds__(256) void ln_kernel(
    const float* __restrict__ x, const float* __restrict__ gamma,
    const float* __restrict__ beta, float* __restrict__ out)
{
    int token = blockIdx.x * 8 + (threadIdx.x >> 5);
    int lane  = threadIdx.x & 31;
    const float4* xr = (const float4*)(x + (size_t)token * C_);
    float4 a = xr[lane];
    float4 b = xr[lane + 32];
    float s  = a.x + a.y + a.z + a.w + b.x + b.y + b.z + b.w;
    float s2 = a.x*a.x + a.y*a.y + a.z*a.z + a.w*a.w
             + b.x*b.x + b.y*b.y + b.z*b.z + b.w*b.w;
#pragma unroll
    for (int o = 16; o; o >>= 1) {
        s  += __shfl_xor_sync(0xffffffffu, s,  o);
        s2 += __shfl_xor_sync(0xffffffffu, s2, o);
    }
    float mu   = s * (1.0f / C_);
    float rstd = rsqrtf(s2 * (1.0f / C_) - mu * mu + 1e-5f);
    float4 g0 = ((const float4*)gamma)[lane], g1 = ((const float4*)gamma)[lane + 32];
    float4 e0 = ((const float4*)beta)[lane],  e1 = ((const float4*)beta)[lane + 32];
    float4 o0, o1;
    o0.x = (a.x-mu)*rstd*g0.x + e0.x; o0.y = (a.y-mu)*rstd*g0.y + e0.y;
    o0.z = (a.z-mu)*rstd*g0.z + e0.z; o0.w = (a.w-mu)*rstd*g0.w + e0.w;
    o1.x = (b.x-mu)*rstd*g1.x + e1.x; o1.y = (b.y-mu)*rstd*g1.y + e1.y;
    o1.z = (b.z-mu)*rstd*g1.z + e1.z; o1.w = (b.w-mu)*rstd*g1.w + e1.w;
    float4* orow = (float4*)(out + (size_t)token * C_);
    orow[lane] = o0; orow[lane + 32] = o1;
}

// ---------------- SGEMM (unchanged, passing) ----------------
__global__ __launch_bounds__(256) void gemm_kernel(
    const float* __restrict__ A, const float* __restrict__ W,
    const float* __restrict__ bias, const float* __restrict__ resid,
    float* __restrict__ out)
{
    __shared__ float As[16][128];
    __shared__ float Bs[16][128];
    int tid = threadIdx.x;
    int m0 = blockIdx.y * 128, n0 = blockIdx.x * 128;
    int ty = tid >> 4, tx = tid & 15;
    float acc[8][8];
#pragma unroll
    for (int i = 0; i < 8; ++i)
#pragma unroll
        for (int j = 0; j < 8; ++j) acc[i][j] = 0.0f;
    for (int k0 = 0; k0 < 256; k0 += 16) {
#pragma unroll
        for (int r = 0; r < 2; ++r) {
            int idx = tid + r * 256;
            int m = idx >> 2, kq = idx & 3;
            float4 v = *(const float4*)(A + (size_t)(m0 + m) * C_ + k0 + kq * 4);
            As[kq*4+0][m] = v.x; As[kq*4+1][m] = v.y;
            As[kq*4+2][m] = v.z; As[kq*4+3][m] = v.w;
        }
#pragma unroll
        for (int r = 0; r < 2; ++r) {
            int idx = tid + r * 256;
            int k = idx >> 5, nq = idx & 31;
            *(float4*)&Bs[k][nq*4] = *(const float4*)(W + (size_t)(k0+k)*C_ + n0 + nq*4);
        }
        __syncthreads();
#pragma unroll
        for (int k = 0; k < 16; ++k) {
            float a[8], b[8];
            *(float4*)&a[0] = *(const float4*)&As[k][ty*8];
            *(float4*)&a[4] = *(const float4*)&As[k][ty*8+4];
            *(float4*)&b[0] = *(const float4*)&Bs[k][tx*8];
            *(float4*)&b[4] = *(const float4*)&Bs[k][tx*8+4];
#pragma unroll
            for (int i = 0; i < 8; ++i)
#pragma unroll
                for (int j = 0; j < 8; ++j) acc[i][j] += a[i] * b[j];
        }
        __syncthreads();
    }
    float bs[8];
    *(float4*)&bs[0] = *(const float4*)(bias + n0 + tx*8);
    *(float4*)&bs[4] = *(const float4*)(bias + n0 + tx*8 + 4);
#pragma unroll
    for (int i = 0; i < 8; ++i) {
        size_t off = (size_t)(m0 + ty*8 + i) * C_ + n0 + tx*8;
        float r0[4], r1[4];
#pragma unroll
        for (int j = 0; j < 4; ++j) r0[j] = acc[i][j] + bs[j];
#pragma unroll
        for (int j = 0; j < 4; ++j) r1[j] = acc[i][j+4] + bs[j+4];
        if (resid) {
            float4 x0 = *(const float4*)(resid + off);
            float4 x1 = *(const float4*)(resid + off + 4);
            r0[0]+=x0.x; r0[1]+=x0.y; r0[2]+=x0.z; r0[3]+=x0.w;
            r1[0]+=x1.x; r1[1]+=x1.y; r1[2]+=x1.z; r1[3]+=x1.w;
        }
        *(float4*)(out + off) = *(float4*)r0;
        *(float4*)(out + off + 4) = *(float4*)r1;
    }
}

// ---------------- fp32 -> bf16 hi/lo split ----------------
__global__ __launch_bounds__(256) void cvt_split_kernel(
    const float* __restrict__ in, unsigned short* __restrict__ hi,
    unsigned short* __restrict__ lo)
{
    size_t i = ((size_t)blockIdx.x * 256 + threadIdx.x) * 4;
    float4 v = *(const float4*)(in + i);
    __nv_bfloat16 h0,h1,h2,h3,l0,l1,l2,l3;
    split2(v.x,h0,l0); split2(v.y,h1,l1); split2(v.z,h2,l2); split2(v.w,h3,l3);
    uint2 hv, lv;
    hv.x = pack2(h0,h1); hv.y = pack2(h2,h3);
    lv.x = pack2(l0,l1); lv.y = pack2(l2,l3);
    *(uint2*)(hi + i) = hv;
    *(uint2*)(lo + i) = lv;
}

// ---------------- mma.sync flash attention (split-bf16, no max-sub) ----------
// 256 thr = 8 warps; warp w owns rows m0+16w..+15. BN=64 keys/iter, C=256.
// SMEM: Qhi 64K | Qlo 64K | KV hi 32K | KV lo 32K  = 192K (+0 static)
#define SM_QH 0
#define SM_QL 65536
#define SM_KH 131072
#define ATTN_SMEM (131072 + 65536)

__global__ __launch_bounds__(256, 1) void attn_mma_kernel(
    const float* __restrict__ Q,
    const unsigned short* __restrict__ KH, const unsigned short* __restrict__ KL,
    const unsigned short* __restrict__ VH, const unsigned short* __restrict__ VL,
    float* __restrict__ O)
{
    extern __shared__ char smc[];
    const uint32_t sb = smem_u32(smc);
    const int tid = threadIdx.x, lane = tid & 31, w = tid >> 5;
    const int b = blockIdx.y, m0 = blockIdx.x * 128;

    // Q: fp32 -> *1/16 -> bf16 hi/lo -> swizzled smem
    {
        const float* Qb = Q + ((size_t)b * HW_ + m0) * C_;
        for (int u = tid; u < 4096; u += 256) {
            int row = u >> 5, cc = u & 31;
            const float4* s4 = (const float4*)(Qb + row * C_ + cc * 8);
            float4 f0 = s4[0], f1 = s4[1];
            float ff[8] = {f0.x,f0.y,f0.z,f0.w,f1.x,f1.y,f1.z,f1.w};
            uint32_t hi[4], lo[4];
#pragma unroll
            for (int i = 0; i < 4; ++i) {
                __nv_bfloat16 ha,la,hb,lb;
                split2(ff[2*i]   * 0.0625f, ha, la);
                split2(ff[2*i+1] * 0.0625f, hb, lb);
                hi[i] = pack2(ha,hb); lo[i] = pack2(la,lb);
            }
            uint32_t sw = (uint32_t)(row * 512 + ((cc ^ (row & 7)) << 4));
            *(uint4*)(smc + SM_QH + sw) = *(uint4*)hi;
            *(uint4*)(smc + SM_QL + sw) = *(uint4*)lo;
        }
    }

    // ldmatrix per-thread geometry
    const int t8 = lane & 7, gq = lane >> 3;
    const int arow  = (w << 4) + ((gq & 1) << 3) + t8;      // A: m = glo*8+r, khalf = ghi
    const uint32_t aoff = sb + SM_QH + arow * 512;
    const int arow7 = arow & 7, akh = gq >> 1;
    const int brow_l = ((gq >> 1) << 3) + t8, bkh = gq & 1; // B(K): n rows, khalf
    const int vrow_l = ((gq & 1) << 3) + t8, vnh = gq >> 1; // B(V,trans): k rows, nhalf

    float oacc[128];
#pragma unroll
    for (int i = 0; i < 128; ++i) oacc[i] = 0.f;
    float l0 = 0.f, l1 = 0.f;

    const unsigned short* KHb = KH + (size_t)b * HW_ * C_;
    const unsigned short* KLb = KL + (size_t)b * HW_ * C_;
    const unsigned short* VHb = VH + (size_t)b * HW_ * C_;
    const unsigned short* VLb = VL + (size_t)b * HW_ * C_;

    for (int kt = 0; kt < 64; ++kt) {
        __syncthreads();                       // prev V reads done; Q visible (iter 0)
        {   // K tile 64x256 hi/lo -> smem
            size_t base = (size_t)kt * 64 * C_;
#pragma unroll
            for (int rq = 0; rq < 8; ++rq) {
                int u = tid + rq * 256;
                int row = u >> 5, cc = u & 31;
                uint32_t sw = (uint32_t)(row * 512 + ((cc ^ (row & 7)) << 4));
                cpa16(sb + SM_KH + sw,          KHb + base + row * C_ + cc * 8);
                cpa16(sb + SM_KH + 32768u + sw, KLb + base + row * C_ + cc * 8);
            }
            CP_COMMIT(); CP_WAIT();
        }
        __syncthreads();

        // ---- S = Q K^T ----
        float sacc[32];
#pragma unroll
        for (int i = 0; i < 32; ++i) sacc[i] = 0.f;
#pragma unroll 1
        for (int kk = 0; kk < 16; ++kk) {
            uint32_t ah[4], al[4];
            uint32_t ad = aoff + (uint32_t)(((2*kk + akh) ^ arow7) << 4);
            LDSM4(ah, ad);
            LDSM4(al, ad + 65536u);
#pragma unroll
            for (int np = 0; np < 4; ++np) {
                int brow = np * 16 + brow_l;
                uint32_t bd = sb + SM_KH +
                    (uint32_t)(brow * 512 + (((2*kk + bkh) ^ (brow & 7)) << 4));
                uint32_t bh[4], bl[4];
                LDSM4(bh, bd);
                LDSM4(bl, bd + 32768u);
                mma16816(&sacc[(2*np)*4],   ah, bh[0], bh[1]);
                mma16816(&sacc[(2*np)*4],   ah, bl[0], bl[1]);
                mma16816(&sacc[(2*np)*4],   al, bh[0], bh[1]);
                mma16816(&sacc[(2*np+1)*4], ah, bh[2], bh[3]);
                mma16816(&sacc[(2*np+1)*4], ah, bl[2], bl[3]);
                mma16816(&sacc[(2*np+1)*4], al, bh[2], bh[3]);
            }
        }

        // ---- softmax (bounded logits: no max-sub) -> P fragments ----
        uint32_t ph[4][4], pl[4][4];
#pragma unroll
        for (int j = 0; j < 4; ++j) {
            float e[8];
#pragma unroll
            for (int i = 0; i < 4; ++i) {
                e[i]   = __expf(sacc[(2*j)*4 + i]);
                e[4+i] = __expf(sacc[(2*j+1)*4 + i]);
            }
            l0 += e[0] + e[1] + e[4] + e[5];
            l1 += e[2] + e[3] + e[6] + e[7];
            __nv_bfloat16 ha,la,hb,lb;
            split2(e[0],ha,la); split2(e[1],hb,lb);
            ph[j][0] = pack2(ha,hb); pl[j][0] = pack2(la,lb);
            split2(e[2],ha,la); split2(e[3],hb,lb);
            ph[j][1] = pack2(ha,hb); pl[j][1] = pack2(la,lb);
            split2(e[4],ha,la); split2(e[5],hb,lb);
            ph[j][2] = pack2(ha,hb); pl[j][2] = pack2(la,lb);
            split2(e[6],ha,la); split2(e[7],hb,lb);
            ph[j][3] = pack2(ha,hb); pl[j][3] = pack2(la,lb);
        }

        __syncthreads();                       // all warps done reading K
        {   // V tile 64x256 hi/lo -> same smem buffer
            size_t base = (size_t)kt * 64 * C_;
#pragma unroll
            for (int rq = 0; rq < 8; ++rq) {
                int u = tid + rq * 256;
                int row = u >> 5, cc = u & 31;
                uint32_t sw = (uint32_t)(row * 512 + ((cc ^ (row & 7)) << 4));
                cpa16(sb + SM_KH + sw,          VHb + base + row * C_ + cc * 8);
                cpa16(sb + SM_KH + 32768u + sw, VLb + base + row * C_ + cc * 8);
            }
            CP_COMMIT(); CP_WAIT();
        }
        __syncthreads();

        // ---- O += P V ----
#pragma unroll
        for (int j = 0; j < 4; ++j) {
            int vrow = j * 16 + vrow_l;
            uint32_t vbase = sb + SM_KH + (uint32_t)(vrow * 512);
            int vrow7 = vrow & 7;
#pragma unroll
            for (int p = 0; p < 16; ++p) {
                uint32_t vd = vbase + (uint32_t)(((2*p + vnh) ^ vrow7) << 4);
                uint32_t bh[4], bl[4];
                LDSM4T(bh, vd);
                LDSM4T(bl, vd + 32768u);
                mma16816(&oacc[(2*p)*4],   ph[j], bh[0], bh[1]);
                mma16816(&oacc[(2*p)*4],   ph[j], bl[0], bl[1]);
                mma16816(&oacc[(2*p)*4],   pl[j], bh[0], bh[1]);
                mma16816(&oacc[(2*p+1)*4], ph[j], bh[2], bh[3]);
                mma16816(&oacc[(2*p+1)*4], ph[j], bl[2], bl[3]);
                mma16816(&oacc[(2*p+1)*4], pl[j], bh[2], bh[3]);
            }
        }
    }

    // ---- epilogue: reduce l over quad, O /= l, store ----
    l0 += __shfl_xor_sync(0xffffffffu, l0, 1);
    l0 += __shfl_xor_sync(0xffffffffu, l0, 2);
    l1 += __shfl_xor_sync(0xffffffffu, l1, 1);
    l1 += __shfl_xor_sync(0xffffffffu, l1, 2);
    float i0 = 1.f / l0, i1 = 1.f / l1;
    int r = lane >> 2, cq = (lane & 3) * 2;
    float* Ob = O + ((size_t)b * HW_ + m0 + w * 16) * C_;
#pragma unroll
    for (int nn = 0; nn < 32; ++nn) {
        float2 v0 = make_float2(oacc[nn*4]   * i0, oacc[nn*4+1] * i0);
        float2 v1 = make_float2(oacc[nn*4+2] * i1, oacc[nn*4+3] * i1);
        *(float2*)(Ob + r * C_ + nn * 8 + cq)       = v0;
        *(float2*)(Ob + (r + 8) * C_ + nn * 8 + cq) = v1;
    }
}

// ---------------- launch ----------------
extern "C" void kernel_launch(void* const* d_in, const int* in_sizes, int n_in,
                              void* d_out, int out_size)
{
    const float* x   = (const float*)d_in[0];
    const float* gam = (const float*)d_in[1];
    const float* bet = (const float*)d_in[2];
    const float* wq  = (const float*)d_in[3];
    const float* bq  = (const float*)d_in[4];
    const float* wk  = (const float*)d_in[5];
    const float* bk  = (const float*)d_in[6];
    const float* wv  = (const float*)d_in[7];
    const float* bv  = (const float*)d_in[8];
    const float* wo  = (const float*)d_in[9];
    const float* bo  = (const float*)d_in[10];
    float* out = (float*)d_out;

    float *h, *q, *k, *v, *ao;
    unsigned short *kh, *kl, *vh, *vl;
    cudaGetSymbolAddress((void**)&h,  g_h);
    cudaGetSymbolAddress((void**)&q,  g_q);
    cudaGetSymbolAddress((void**)&k,  g_k);
    cudaGetSymbolAddress((void**)&v,  g_v);
    cudaGetSymbolAddress((void**)&ao, g_ao);
    cudaGetSymbolAddress((void**)&kh, g_kh);
    cudaGetSymbolAddress((void**)&kl, g_kl);
    cudaGetSymbolAddress((void**)&vh, g_vh);
    cudaGetSymbolAddress((void**)&vl, g_vl);

    cudaFuncSetAttribute(attn_mma_kernel,
                         cudaFuncAttributeMaxDynamicSharedMemorySize, ATTN_SMEM);

    ln_kernel<<<NT_ / 8, 256>>>(x, gam, bet, h);

    dim3 gg(C_ / 128, NT_ / 128);
    gemm_kernel<<<gg, 256>>>(h, wq, bq, nullptr, q);
    gemm_kernel<<<gg, 256>>>(h, wk, bk, nullptr, k);
    gemm_kernel<<<gg, 256>>>(h, wv, bv, nullptr, v);

    cvt_split_kernel<<<(NT_ * C_) / (256 * 4), 256>>>(k, kh, kl);
    cvt_split_kernel<<<(NT_ * C_) / (256 * 4), 256>>>(v, vh, vl);

    attn_mma_kernel<<<dim3(HW_ / 128, B_), 256, ATTN_SMEM>>>(q, kh, kl, vh, vl, ao);

    gemm_kernel<<<gg, 256>>>(ao, wo, bo, x, out);
}

// round 9
// speedup vs baseline: 3.8358x; 1.1659x over previous
#include <cuda_runtime.h>
#include <cuda_bf16.h>
#include <math.h>
#include <stdint.h>

#define B_   8
#define HW_  4096
#define C_   256
#define NT_  (B_ * HW_)

static __device__ float g_h [(size_t)NT_ * C_];
static __device__ float g_q [(size_t)NT_ * C_];
static __device__ float g_ao[(size_t)NT_ * C_];
static __device__ unsigned short g_kh[(size_t)NT_ * C_];
static __device__ unsigned short g_kl[(size_t)NT_ * C_];
static __device__ unsigned short g_vh[(size_t)NT_ * C_];
static __device__ unsigned short g_vl[(size_t)NT_ * C_];

// ---------------- helpers (sm_80-level PTX only) ----------------
__device__ __forceinline__ uint32_t smem_u32(const void* p) {
    uint32_t a;
    asm("{ .reg .u64 t; cvta.to.shared.u64 t, %1; cvt.u32.u64 %0, t; }" : "=r"(a) : "l"(p));
    return a;
}
__device__ __forceinline__ void cpa16(uint32_t s, const void* g) {
    asm volatile("cp.async.cg.shared.global [%0], [%1], 16;" :: "r"(s), "l"(g));
}
#define CP_COMMIT() asm volatile("cp.async.commit_group;" ::: "memory")
#define CP_WAIT()   asm volatile("cp.async.wait_group 0;" ::: "memory")
#define LDSM4(R, A) \
    asm volatile("ldmatrix.sync.aligned.m8n8.x4.shared.b16 {%0,%1,%2,%3}, [%4];" \
        : "=r"((R)[0]), "=r"((R)[1]), "=r"((R)[2]), "=r"((R)[3]) : "r"(A))
#define LDSM4T(R, A) \
    asm volatile("ldmatrix.sync.aligned.m8n8.x4.trans.shared.b16 {%0,%1,%2,%3}, [%4];" \
        : "=r"((R)[0]), "=r"((R)[1]), "=r"((R)[2]), "=r"((R)[3]) : "r"(A))
__device__ __forceinline__ void mma16816(float* c, const uint32_t* a, uint32_t b0, uint32_t b1) {
    asm volatile("mma.sync.aligned.m16n8k16.row.col.f32.bf16.bf16.f32 "
                 "{%0,%1,%2,%3}, {%4,%5,%6,%7}, {%8,%9}, {%0,%1,%2,%3};"
                 : "+f"(c[0]), "+f"(c[1]), "+f"(c[2]), "+f"(c[3])
                 : "r"(a[0]), "r"(a[1]), "r"(a[2]), "r"(a[3]), "r"(b0), "r"(b1));
}
__device__ __forceinline__ uint32_t pack2(__nv_bfloat16 a, __nv_bfloat16 b) {
    __nv_bfloat162 t; t.x = a; t.y = b;
    return *reinterpret_cast<uint32_t*>(&t);
}
__device__ __forceinline__ void split2(float f, __nv_bfloat16& h, __nv_bfloat16& l) {
    h = __float2bfloat16(f);
    l = __float2bfloat16(f - __bfloat162float(h));
}

// ---------------- LayerNorm ----------------
__global__ __launch_bounds__(256) void ln_kernel(
    const float* __restrict__ x, const float* __restrict__ gamma,
    const float* __restrict__ beta, float* __restrict__ out)
{
    int token = blockIdx.x * 8 + (threadIdx.x >> 5);
    int lane  = threadIdx.x & 31;
    const float4* xr = (const float4*)(x + (size_t)token * C_);
    float4 a = xr[lane];
    float4 b = xr[lane + 32];
    float s  = a.x + a.y + a.z + a.w + b.x + b.y + b.z + b.w;
    float s2 = a.x*a.x + a.y*a.y + a.z*a.z + a.w*a.w
             + b.x*b.x + b.y*b.y + b.z*b.z + b.w*b.w;
#pragma unroll
    for (int o = 16; o; o >>= 1) {
        s  += __shfl_xor_sync(0xffffffffu, s,  o);
        s2 += __shfl_xor_sync(0xffffffffu, s2, o);
    }
    float mu   = s * (1.0f / C_);
    float rstd = rsqrtf(s2 * (1.0f / C_) - mu * mu + 1e-5f);
    float4 g0 = ((const float4*)gamma)[lane], g1 = ((const float4*)gamma)[lane + 32];
    float4 e0 = ((const float4*)beta)[lane],  e1 = ((const float4*)beta)[lane + 32];
    float4 o0, o1;
    o0.x = (a.x-mu)*rstd*g0.x + e0.x; o0.y = (a.y-mu)*rstd*g0.y + e0.y;
    o0.z = (a.z-mu)*rstd*g0.z + e0.z; o0.w = (a.w-mu)*rstd*g0.w + e0.w;
    o1.x = (b.x-mu)*rstd*g1.x + e1.x; o1.y = (b.y-mu)*rstd*g1.y + e1.y;
    o1.z = (b.z-mu)*rstd*g1.z + e1.z; o1.w = (b.w-mu)*rstd*g1.w + e1.w;
    float4* orow = (float4*)(out + (size_t)token * C_);
    orow[lane] = o0; orow[lane + 32] = o1;
}

// ---------------- split-bf16 mma.sync GEMM ----------------
// out[M,256] = A[M,256] @ W[256,256] + bias (+resid). 3-term hi/lo split.
// 8 warps: wm=w&3 (32 rows), wn=w>>2 (64 cols). Warp tile 32x64 = 2 m16 x 8 n8.
// BK=32 per stage; gmem->reg staged, convert->smem, LDG for s+1 hidden under MMA.
#define GM_AH 0
#define GM_AL 10240
#define GM_WH 20480
#define GM_WL 29184
#define GEMM_SMEM 37888

__global__ __launch_bounds__(256) void gemm_bf16_kernel(
    const float* __restrict__ A, const float* __restrict__ W,
    const float* __restrict__ bias, const float* __restrict__ resid,
    float* __restrict__ outf,
    unsigned short* __restrict__ ohi, unsigned short* __restrict__ olo)
{
    __shared__ char gsm[GEMM_SMEM];
    const uint32_t sb = smem_u32(gsm);
    const int tid = threadIdx.x, lane = tid & 31, w = tid >> 5;
    const int wm = w & 3, wn = w >> 2;
    const int m0 = blockIdx.y * 128, n0 = blockIdx.x * 128;
    const int t8 = lane & 7, gq = lane >> 3;

    float acc[2][8][4];
#pragma unroll
    for (int i = 0; i < 2; ++i)
#pragma unroll
        for (int j = 0; j < 8; ++j)
#pragma unroll
            for (int q = 0; q < 4; ++q) acc[i][j][q] = 0.f;

    float4 ra[4], rw[4];
#pragma unroll
    for (int r = 0; r < 4; ++r) {
        int idx = tid + r * 256;
        ra[r] = *(const float4*)(A + (size_t)(m0 + (idx>>3)) * C_ + (idx&7)*4);
        rw[r] = *(const float4*)(W + (size_t)(idx>>5) * C_ + n0 + (idx&31)*4);
    }

    for (int s = 0; s < 8; ++s) {
        __syncthreads();
#pragma unroll
        for (int r = 0; r < 4; ++r) {
            int idx = tid + r * 256;
            __nv_bfloat16 h0,l0,h1,l1,h2,l2,h3,l3;
            split2(ra[r].x,h0,l0); split2(ra[r].y,h1,l1);
            split2(ra[r].z,h2,l2); split2(ra[r].w,h3,l3);
            uint2 hv, lv;
            hv.x = pack2(h0,h1); hv.y = pack2(h2,h3);
            lv.x = pack2(l0,l1); lv.y = pack2(l2,l3);
            int m = idx >> 3, kq = idx & 7;
            *(uint2*)(gsm + GM_AH + m*80 + kq*8) = hv;
            *(uint2*)(gsm + GM_AL + m*80 + kq*8) = lv;
            split2(rw[r].x,h0,l0); split2(rw[r].y,h1,l1);
            split2(rw[r].z,h2,l2); split2(rw[r].w,h3,l3);
            hv.x = pack2(h0,h1); hv.y = pack2(h2,h3);
            lv.x = pack2(l0,l1); lv.y = pack2(l2,l3);
            int k = idx >> 5, nq = idx & 31;
            *(uint2*)(gsm + GM_WH + k*272 + nq*8) = hv;
            *(uint2*)(gsm + GM_WL + k*272 + nq*8) = lv;
        }
        __syncthreads();
        if (s < 7) {
            int k0n = (s + 1) * 32;
#pragma unroll
            for (int r = 0; r < 4; ++r) {
                int idx = tid + r * 256;
                ra[r] = *(const float4*)(A + (size_t)(m0 + (idx>>3)) * C_ + k0n + (idx&7)*4);
                rw[r] = *(const float4*)(W + (size_t)(k0n + (idx>>5)) * C_ + n0 + (idx&31)*4);
            }
        }
#pragma unroll
        for (int kk = 0; kk < 2; ++kk) {
            uint32_t ah[2][4], al[2][4];
#pragma unroll
            for (int mt = 0; mt < 2; ++mt) {
                int row = wm*32 + mt*16 + ((gq&1)<<3) + t8;
                uint32_t ad = sb + GM_AH + row*80 + kk*32 + (gq>>1)*16;
                LDSM4(ah[mt], ad);
                LDSM4(al[mt], ad + (GM_AL - GM_AH));
            }
            int rowk = kk*16 + ((gq&1)<<3) + t8;
#pragma unroll
            for (int j = 0; j < 4; ++j) {
                uint32_t bd = sb + GM_WH + rowk*272 + wn*128 + (2*j + (gq>>1))*16;
                uint32_t bh[4], bl[4];
                LDSM4T(bh, bd);
                LDSM4T(bl, bd + (GM_WL - GM_WH));
#pragma unroll
                for (int mt = 0; mt < 2; ++mt) {
                    mma16816(acc[mt][2*j],   ah[mt], bh[0], bh[1]);
                    mma16816(acc[mt][2*j],   ah[mt], bl[0], bl[1]);
                    mma16816(acc[mt][2*j],   al[mt], bh[0], bh[1]);
                    mma16816(acc[mt][2*j+1], ah[mt], bh[2], bh[3]);
                    mma16816(acc[mt][2*j+1], ah[mt], bl[2], bl[3]);
                    mma16816(acc[mt][2*j+1], al[mt], bh[2], bh[3]);
                }
            }
        }
    }

#pragma unroll
    for (int mt = 0; mt < 2; ++mt)
#pragma unroll
        for (int n8 = 0; n8 < 8; ++n8) {
            int row = m0 + wm*32 + mt*16 + (lane >> 2);
            int col = n0 + wn*64 + n8*8 + (lane & 3)*2;
            size_t o0 = (size_t)row * C_ + col, o1 = o0 + 8 * C_;
            float b0 = bias[col], b1 = bias[col + 1];
            float v00 = acc[mt][n8][0] + b0, v01 = acc[mt][n8][1] + b1;
            float v10 = acc[mt][n8][2] + b0, v11 = acc[mt][n8][3] + b1;
            if (resid) {
                v00 += resid[o0]; v01 += resid[o0 + 1];
                v10 += resid[o1]; v11 += resid[o1 + 1];
            }
            if (outf) {
                *(float2*)(outf + o0) = make_float2(v00, v01);
                *(float2*)(outf + o1) = make_float2(v10, v11);
            }
            if (ohi) {
                __nv_bfloat16 h0,l0,h1,l1;
                split2(v00,h0,l0); split2(v01,h1,l1);
                *(uint32_t*)(ohi + o0) = pack2(h0,h1);
                *(uint32_t*)(olo + o0) = pack2(l0,l1);
                split2(v10,h0,l0); split2(v11,h1,l1);
                *(uint32_t*)(ohi + o1) = pack2(h0,h1);
                *(uint32_t*)(olo + o1) = pack2(l0,l1);
            }
        }
}

// ---------------- mma.sync flash attention (split-bf16, no max-sub) ----------
#define SM_QH 0
#define SM_QL 65536
#define SM_KH 131072
#define ATTN_SMEM (131072 + 65536)

__global__ __launch_bounds__(256, 1) void attn_mma_kernel(
    const float* __restrict__ Q,
    const unsigned short* __restrict__ KH, const unsigned short* __restrict__ KL,
    const unsigned short* __restrict__ VH, const unsigned short* __restrict__ VL,
    float* __restrict__ O)
{
    extern __shared__ char smc[];
    const uint32_t sb = smem_u32(smc);
    const int tid = threadIdx.x, lane = tid & 31, w = tid >> 5;
    const int b = blockIdx.y, m0 = blockIdx.x * 128;

    // Q: fp32 -> *1/16 -> bf16 hi/lo -> swizzled smem
    {
        const float* Qb = Q + ((size_t)b * HW_ + m0) * C_;
        for (int u = tid; u < 4096; u += 256) {
            int row = u >> 5, cc = u & 31;
            const float4* s4 = (const float4*)(Qb + row * C_ + cc * 8);
            float4 f0 = s4[0], f1 = s4[1];
            float ff[8] = {f0.x,f0.y,f0.z,f0.w,f1.x,f1.y,f1.z,f1.w};
            uint32_t hi[4], lo[4];
#pragma unroll
            for (int i = 0; i < 4; ++i) {
                __nv_bfloat16 ha,la,hb,lb;
                split2(ff[2*i]   * 0.0625f, ha, la);
                split2(ff[2*i+1] * 0.0625f, hb, lb);
                hi[i] = pack2(ha,hb); lo[i] = pack2(la,lb);
            }
            uint32_t sw = (uint32_t)(row * 512 + ((cc ^ (row & 7)) << 4));
            *(uint4*)(smc + SM_QH + sw) = *(uint4*)hi;
            *(uint4*)(smc + SM_QL + sw) = *(uint4*)lo;
        }
    }

    const int t8 = lane & 7, gq = lane >> 3;
    const int arow  = (w << 4) + ((gq & 1) << 3) + t8;
    const uint32_t aoff = sb + SM_QH + arow * 512;
    const int arow7 = arow & 7, akh = gq >> 1;
    const int brow_l = ((gq >> 1) << 3) + t8, bkh = gq & 1;
    const int vrow_l = ((gq & 1) << 3) + t8, vnh = gq >> 1;

    float oacc[128];
#pragma unroll
    for (int i = 0; i < 128; ++i) oacc[i] = 0.f;
    float l0 = 0.f, l1 = 0.f;

    const unsigned short* KHb = KH + (size_t)b * HW_ * C_;
    const unsigned short* KLb = KL + (size_t)b * HW_ * C_;
    const unsigned short* VHb = VH + (size_t)b * HW_ * C_;
    const unsigned short* VLb = VL + (size_t)b * HW_ * C_;

    for (int kt = 0; kt < 64; ++kt) {
        __syncthreads();                       // prev V reads done
        {   // K tile 64x256 hi/lo -> smem
            size_t base = (size_t)kt * 64 * C_;
#pragma unroll
            for (int rq = 0; rq < 8; ++rq) {
                int u = tid + rq * 256;
                int row = u >> 5, cc = u & 31;
                uint32_t sw = (uint32_t)(row * 512 + ((cc ^ (row & 7)) << 4));
                cpa16(sb + SM_KH + sw,          KHb + base + row * C_ + cc * 8);
                cpa16(sb + SM_KH + 32768u + sw, KLb + base + row * C_ + cc * 8);
            }
            CP_COMMIT(); CP_WAIT();
        }
        __syncthreads();

        // ---- S = Q K^T ----
        float sacc[32];
#pragma unroll
        for (int i = 0; i < 32; ++i) sacc[i] = 0.f;
#pragma unroll 1
        for (int kk = 0; kk < 16; ++kk) {
            uint32_t ah[4], al[4];
            uint32_t ad = aoff + (uint32_t)(((2*kk + akh) ^ arow7) << 4);
            LDSM4(ah, ad);
            LDSM4(al, ad + 65536u);
#pragma unroll
            for (int np = 0; np < 4; ++np) {
                int brow = np * 16 + brow_l;
                uint32_t bd = sb + SM_KH +
                    (uint32_t)(brow * 512 + (((2*kk + bkh) ^ (brow & 7)) << 4));
                uint32_t bh[4], bl[4];
                LDSM4(bh, bd);
                LDSM4(bl, bd + 32768u);
                mma16816(&sacc[(2*np)*4],   ah, bh[0], bh[1]);
                mma16816(&sacc[(2*np)*4],   ah, bl[0], bl[1]);
                mma16816(&sacc[(2*np)*4],   al, bh[0], bh[1]);
                mma16816(&sacc[(2*np+1)*4], ah, bh[2], bh[3]);
                mma16816(&sacc[(2*np+1)*4], ah, bl[2], bl[3]);
                mma16816(&sacc[(2*np+1)*4], al, bh[2], bh[3]);
            }
        }

        __syncthreads();                       // all warps done reading K
        {   // V tile -> same buffer, overlapped with softmax below
            size_t base = (size_t)kt * 64 * C_;
#pragma unroll
            for (int rq = 0; rq < 8; ++rq) {
                int u = tid + rq * 256;
                int row = u >> 5, cc = u & 31;
                uint32_t sw = (uint32_t)(row * 512 + ((cc ^ (row & 7)) << 4));
                cpa16(sb + SM_KH + sw,          VHb + base + row * C_ + cc * 8);
                cpa16(sb + SM_KH + 32768u + sw, VLb + base + row * C_ + cc * 8);
            }
            CP_COMMIT();
        }

        // ---- softmax (bounded logits: no max-sub) -> P fragments ----
        uint32_t ph[4][4], pl[4][4];
#pragma unroll
        for (int j = 0; j < 4; ++j) {
            float e[8];
#pragma unroll
            for (int i = 0; i < 4; ++i) {
                e[i]   = __expf(sacc[(2*j)*4 + i]);
                e[4+i] = __expf(sacc[(2*j+1)*4 + i]);
            }
            l0 += e[0] + e[1] + e[4] + e[5];
            l1 += e[2] + e[3] + e[6] + e[7];
            __nv_bfloat16 ha,la,hb,lb;
            split2(e[0],ha,la); split2(e[1],hb,lb);
            ph[j][0] = pack2(ha,hb); pl[j][0] = pack2(la,lb);
            split2(e[2],ha,la); split2(e[3],hb,lb);
            ph[j][1] = pack2(ha,hb); pl[j][1] = pack2(la,lb);
            split2(e[4],ha,la); split2(e[5],hb,lb);
            ph[j][2] = pack2(ha,hb); pl[j][2] = pack2(la,lb);
            split2(e[6],ha,la); split2(e[7],hb,lb);
            ph[j][3] = pack2(ha,hb); pl[j][3] = pack2(la,lb);
        }

        CP_WAIT();
        __syncthreads();

        // ---- O += P V ----
#pragma unroll
        for (int j = 0; j < 4; ++j) {
            int vrow = j * 16 + vrow_l;
            uint32_t vbase = sb + SM_KH + (uint32_t)(vrow * 512);
            int vrow7 = vrow & 7;
#pragma unroll
            for (int p = 0; p < 16; ++p) {
                uint32_t vd = vbase + (uint32_t)(((2*p + vnh) ^ vrow7) << 4);
                uint32_t bh[4], bl[4];
                LDSM4T(bh, vd);
                LDSM4T(bl, vd + 32768u);
                mma16816(&oacc[(2*p)*4],   ph[j], bh[0], bh[1]);
                mma16816(&oacc[(2*p)*4],   ph[j], bl[0], bl[1]);
                mma16816(&oacc[(2*p)*4],   pl[j], bh[0], bh[1]);
                mma16816(&oacc[(2*p+1)*4], ph[j], bh[2], bh[3]);
                mma16816(&oacc[(2*p+1)*4], ph[j], bl[2], bl[3]);
                mma16816(&oacc[(2*p+1)*4], pl[j], bh[2], bh[3]);
            }
        }
    }

    // ---- epilogue ----
    l0 += __shfl_xor_sync(0xffffffffu, l0, 1);
    l0 += __shfl_xor_sync(0xffffffffu, l0, 2);
    l1 += __shfl_xor_sync(0xffffffffu, l1, 1);
    l1 += __shfl_xor_sync(0xffffffffu, l1, 2);
    float i0 = 1.f / l0, i1 = 1.f / l1;
    int r = lane >> 2, cq = (lane & 3) * 2;
    float* Ob = O + ((size_t)b * HW_ + m0 + w * 16) * C_;
#pragma unroll
    for (int nn = 0; nn < 32; ++nn) {
        float2 v0 = make_float2(oacc[nn*4]   * i0, oacc[nn*4+1] * i0);
        float2 v1 = make_float2(oacc[nn*4+2] * i1, oacc[nn*4+3] * i1);
        *(float2*)(Ob + r * C_ + nn * 8 + cq)       = v0;
        *(float2*)(Ob + (r + 8) * C_ + nn * 8 + cq) = v1;
    }
}

// ---------------- launch ----------------
extern "C" void kernel_launch(void* const* d_in, const int* in_sizes, int n_in,
                              void* d_out, int out_size)
{
    const float* x   = (const float*)d_in[0];
    const float* gam = (const float*)d_in[1];
    const float* bet = (const float*)d_in[2];
    const float* wq  = (const float*)d_in[3];
    const float* bq  = (const float*)d_in[4];
    const float* wk  = (const float*)d_in[5];
    const float* bk  = (const float*)d_in[6];
    const float* wv  = (const float*)d_in[7];
    const float* bv  = (const float*)d_in[8];
    const float* wo  = (const float*)d_in[9];
    const float* bo  = (const float*)d_in[10];
    float* out = (float*)d_out;

    float *h, *q, *ao;
    unsigned short *kh, *kl, *vh, *vl;
    cudaGetSymbolAddress((void**)&h,  g_h);
    cudaGetSymbolAddress((void**)&q,  g_q);
    cudaGetSymbolAddress((void**)&ao, g_ao);
    cudaGetSymbolAddress((void**)&kh, g_kh);
    cudaGetSymbolAddress((void**)&kl, g_kl);
    cudaGetSymbolAddress((void**)&vh, g_vh);
    cudaGetSymbolAddress((void**)&vl, g_vl);

    cudaFuncSetAttribute(attn_mma_kernel,
                         cudaFuncAttributeMaxDynamicSharedMemorySize, ATTN_SMEM);

    ln_kernel<<<NT_ / 8, 256>>>(x, gam, bet, h);

    dim3 gg(C_ / 128, NT_ / 128);   // (2, 256)
    gemm_bf16_kernel<<<gg, 256>>>(h, wq, bq, nullptr, q, nullptr, nullptr);
    gemm_bf16_kernel<<<gg, 256>>>(h, wk, bk, nullptr, nullptr, kh, kl);
    gemm_bf16_kernel<<<gg, 256>>>(h, wv, bv, nullptr, nullptr, vh, vl);

    attn_mma_kernel<<<dim3(HW_ / 128, B_), 256, ATTN_SMEM>>>(q, kh, kl, vh, vl, ao);

    gemm_bf16_kernel<<<gg, 256>>>(ao, wo, bo, x, out, nullptr, nullptr);
}